// round 9
// baseline (speedup 1.0000x reference)
#include <cuda_runtime.h>
#include <cuda_bf16.h>
#include <cstdint>

#define D 256
#define BMAX 32768
#define NNEG 16
#define CAND 17
#define TEMP_INV (1.0f/0.07f)
#define TPB 512
#define BM 128
#define AST 132   // activation row stride, u32 (528B: 33x16B, mod8=1 -> ldsm conflict-free)
#define WST 20    // weight row stride, u32 (80B: 5x16B, mod8=5 -> conflict-free)
#define TAU 5e-4f
#define FCAP 16384

// prepped split-weight image offsets (u32), chunk=32 k, layout [chunk][n][WST]
#define OW1X 0
#define OW1Y 40960
#define OW2  81920
#define OW3  102400
#define WTOT 107520

__device__ uint32_t g_WH[WTOT], g_WL[WTOT];
__device__ float g_A[BMAX*256];
__device__ float g_E[BMAX*CAND];
__device__ float g_row[4*BMAX];
__device__ int g_nflag, g_flags[FCAP];

__device__ __forceinline__ float gelu(float x){ return 0.5f*x*(1.0f+erff(x*0.70710678118654752f)); }
__device__ __forceinline__ uint32_t smem_u32(const void* p){
    uint32_t a; asm("{ .reg .u64 t; cvta.to.shared.u64 t, %1; cvt.u32.u64 %0, t; }":"=r"(a):"l"(p)); return a;
}
__device__ __forceinline__ unsigned pack_hi(float x, float y){
    return (unsigned)__bfloat16_as_ushort(__float2bfloat16(x)) |
           ((unsigned)__bfloat16_as_ushort(__float2bfloat16(y))<<16);
}
__device__ __forceinline__ unsigned pack_lo(float x, float y){
    float xr = x - __bfloat162float(__float2bfloat16(x));
    float yr = y - __bfloat162float(__float2bfloat16(y));
    return pack_hi(xr, yr);
}
__device__ __forceinline__ void mma16816(float* c, const unsigned* a, const unsigned* b){
    asm volatile("mma.sync.aligned.m16n8k16.row.col.f32.bf16.bf16.f32 "
        "{%0,%1,%2,%3},{%4,%5,%6,%7},{%8,%9},{%0,%1,%2,%3};"
        : "+f"(c[0]),"+f"(c[1]),"+f"(c[2]),"+f"(c[3])
        : "r"(a[0]),"r"(a[1]),"r"(a[2]),"r"(a[3]),"r"(b[0]),"r"(b[1]));
}
__device__ __forceinline__ void ldsm4(unsigned* r, uint32_t a){
    asm volatile("ldmatrix.sync.aligned.m8n8.x4.shared.b16 {%0,%1,%2,%3},[%4];"
        : "=r"(r[0]),"=r"(r[1]),"=r"(r[2]),"=r"(r[3]) : "r"(a));
}
__device__ __forceinline__ void ldsm2(unsigned* r, uint32_t a){
    asm volatile("ldmatrix.sync.aligned.m8n8.x2.shared.b16 {%0,%1},[%2];"
        : "=r"(r[0]),"=r"(r[1]) : "r"(a));
}

// One split-GEMM layer: D(128 x NT*16) = act(128 x KC*32) @ W^T, fp32 acc.
// Warps: 8 along M (16 rows each) x 2 along N. 3 mmas per tile (AhWh,AlWh,AhWl).
template<int NT,int KC>
__device__ __forceinline__ void layer_mma(uint32_t aHb, uint32_t aLb,
    uint32_t wHb, uint32_t wLb, uint32_t* wHs, uint32_t* wLs,
    const uint32_t* gH, const uint32_t* gL, float* acc){
    const int tid=threadIdx.x, lane=tid&31, w=tid>>5;
    const int mrow=(w&7)*16, ngrp=w>>3;
    const int NROWS=NT*16;
#pragma unroll
    for(int i=0;i<NT*4;++i) acc[i]=0.f;
    for(int kc=0;kc<KC;++kc){
        __syncthreads();
        const uint4* sH=(const uint4*)(gH + kc*NROWS*WST);
        const uint4* sL=(const uint4*)(gL + kc*NROWS*WST);
        for(int i=tid;i<NROWS*WST/4;i+=TPB){ ((uint4*)wHs)[i]=__ldg(sH+i); ((uint4*)wLs)[i]=__ldg(sL+i); }
        __syncthreads();
#pragma unroll
        for(int kt=0;kt<2;++kt){
            unsigned ah[4],al[4];
            uint32_t ao=((mrow+(lane&7)+8*((lane>>3)&1))*AST + kc*16+kt*8+(lane>>4)*4)*4u;
            ldsm4(ah,aHb+ao); ldsm4(al,aLb+ao);
#pragma unroll
            for(int nt=0;nt<NT;++nt){
                int n0=ngrp*NT*8+nt*8;
                uint32_t wo=((n0+(lane&7))*WST + kt*8+((lane>>3)&1)*4)*4u;
                unsigned wh[2],wl[2];
                ldsm2(wh,wHb+wo); ldsm2(wl,wLb+wo);
                float* c=acc+nt*4;
                mma16816(c,ah,wh); mma16816(c,al,wh); mma16816(c,ah,wl);
            }
        }
    }
    __syncthreads();
}

// ---- kernel 0: split weights into bf16 hi/lo ldsm-ready images -------------
__global__ void prep_w(const float* __restrict__ W1,const float* __restrict__ W2,
                       const float* __restrict__ W3){
    int i=blockIdx.x*blockDim.x+threadIdx.x;
    if(i==0) g_nflag=0;
    if(i>=WTOT) return;
    int n,kp,k; const float* src;
    if(i<OW1Y){ int ch=i/5120, rem=i%5120; n=rem/20; kp=rem%20; k=ch*32+kp*2; src=W1+n*512+k; }
    else if(i<OW2){ int j=i-OW1Y, ch=j/5120, rem=j%5120; n=rem/20; kp=rem%20; k=ch*32+kp*2; src=W1+n*512+256+k; }
    else if(i<OW3){ int j=i-OW2, ch=j/2560, rem=j%2560; n=rem/20; kp=rem%20; k=ch*32+kp*2; src=W2+n*256+k; }
    else { int j=i-OW3, ch=j/1280, rem=j%1280; n=rem/20; kp=rem%20; k=ch*32+kp*2; src=W3+n*128+k; }
    float v0=0.f, v1=0.f;
    if(kp<16){ v0=__ldg(src); v1=__ldg(src+1); }
    g_WH[i]=pack_hi(v0,v1); g_WL[i]=pack_lo(v0,v1);
}

// ---- kernel 1: A = anchor @ W1x^T + b1 (tensor) ----------------------------
__global__ __launch_bounds__(TPB,1) void anchor_tc(const float* __restrict__ anchor,
                                                   const float* __restrict__ b1,int B){
    extern __shared__ uint32_t sm[];
    uint32_t* aH=sm; uint32_t* aL=aH+BM*AST; uint32_t* wHs=aL+BM*AST; uint32_t* wLs=wHs+256*WST;
    uint32_t aHb=smem_u32(aH),aLb=smem_u32(aL),wHb=smem_u32(wHs),wLb=smem_u32(wLs);
    const int tid=threadIdx.x, lane=tid&31, w=tid>>5;
    const int mrow=(w&7)*16, ngrp=w>>3;
    const int r0=blockIdx.x*BM;
    {   int r=tid>>2, seg=tid&3;
        int rr=r0+r; if(rr>=B) rr=B-1;
        const float2* y=(const float2*)(anchor+(size_t)rr*D);
#pragma unroll
        for(int q=0;q<32;++q){ float2 v=__ldg(y+seg+4*q);
            int j2=r*AST+seg+4*q; aH[j2]=pack_hi(v.x,v.y); aL[j2]=pack_lo(v.x,v.y); }
    }
    float acc[64];
    layer_mma<16,8>(aHb,aLb,wHb,wLb,wHs,wLs,g_WH+OW1X,g_WL+OW1X,acc);
    int ra=r0+mrow+(lane>>2), rb=ra+8;
#pragma unroll
    for(int nt=0;nt<16;++nt){
        int c=ngrp*128+nt*8+(lane&3)*2;
        float2 bb=*(const float2*)(b1+c);
        if(ra<B) *(float2*)&g_A[(size_t)ra*256+c]=make_float2(acc[nt*4+0]+bb.x,acc[nt*4+1]+bb.y);
        if(rb<B) *(float2*)&g_A[(size_t)rb*256+c]=make_float2(acc[nt*4+2]+bb.x,acc[nt*4+3]+bb.y);
    }
}

// ---- kernel 2: fused 4-layer MLP, 128 pairs/CTA (tensor) -------------------
__global__ __launch_bounds__(TPB,1) void mlp_tc(const float* __restrict__ pos,
    const float* __restrict__ neg,const float* __restrict__ b2,
    const float* __restrict__ b3,const float* __restrict__ W4,
    const float* __restrict__ b4,int B){
    extern __shared__ uint32_t sm[];
    uint32_t* aH=sm; uint32_t* aL=aH+BM*AST; uint32_t* wHs=aL+BM*AST; uint32_t* wLs=wHs+256*WST;
    float* hb=(float*)(wLs+256*WST);   // [128][68] fp32 h3
    uint32_t aHb=smem_u32(aH),aLb=smem_u32(aL),wHb=smem_u32(wHs),wLb=smem_u32(wLs);
    const int tid=threadIdx.x, lane=tid&31, w=tid>>5;
    const int mrow=(w&7)*16, ngrp=w>>3;
    const int P=B*CAND, p0=blockIdx.x*BM;
    {   int r=tid>>2, seg=tid&3;
        int p=p0+r; if(p>=P)p=P-1; int rr=p/CAND, c=p-rr*CAND;
        const float* yp = (c==0)? pos+(size_t)rr*D : neg+((size_t)rr*NNEG+(c-1))*D;
        const float2* y=(const float2*)yp;
#pragma unroll
        for(int q=0;q<32;++q){ float2 v=__ldg(y+seg+4*q);
            int j2=r*AST+seg+4*q; aH[j2]=pack_hi(v.x,v.y); aL[j2]=pack_lo(v.x,v.y); }
    }
    float acc[64];
    const int rl=mrow+(lane>>2);
    // L1: h1 = gelu(Y@W1y^T + A[row])   K=256 N=256
    layer_mma<16,8>(aHb,aLb,wHb,wLb,wHs,wLs,g_WH+OW1Y,g_WL+OW1Y,acc);
    {   int pa=p0+rl; if(pa>=P)pa=P-1; int rowa=pa/CAND;
        int pb=p0+rl+8; if(pb>=P)pb=P-1; int rowb=pb/CAND;
#pragma unroll
        for(int nt=0;nt<16;++nt){
            int c=ngrp*128+nt*8+(lane&3)*2;
            float2 a0=*(const float2*)&g_A[(size_t)rowa*256+c];
            float2 a1=*(const float2*)&g_A[(size_t)rowb*256+c];
            float h0=gelu(acc[nt*4+0]+a0.x), h1=gelu(acc[nt*4+1]+a0.y);
            float h2=gelu(acc[nt*4+2]+a1.x), h3=gelu(acc[nt*4+3]+a1.y);
            int j2=c>>1;
            aH[rl*AST+j2]=pack_hi(h0,h1);     aL[rl*AST+j2]=pack_lo(h0,h1);
            aH[(rl+8)*AST+j2]=pack_hi(h2,h3); aL[(rl+8)*AST+j2]=pack_lo(h2,h3);
        }
    }
    // L2: h2 = gelu(h1@W2^T + b2)   K=256 N=128
    layer_mma<8,8>(aHb,aLb,wHb,wLb,wHs,wLs,g_WH+OW2,g_WL+OW2,acc);
#pragma unroll
    for(int nt=0;nt<8;++nt){
        int c=ngrp*64+nt*8+(lane&3)*2;
        float2 bb=*(const float2*)(b2+c);
        float h0=gelu(acc[nt*4+0]+bb.x), h1=gelu(acc[nt*4+1]+bb.y);
        float h2=gelu(acc[nt*4+2]+bb.x), h3=gelu(acc[nt*4+3]+bb.y);
        int j2=c>>1;
        aH[rl*AST+j2]=pack_hi(h0,h1);     aL[rl*AST+j2]=pack_lo(h0,h1);
        aH[(rl+8)*AST+j2]=pack_hi(h2,h3); aL[(rl+8)*AST+j2]=pack_lo(h2,h3);
    }
    // L3: h3 = gelu(h2@W3^T + b3)   K=128 N=64  (fp32 to hb)
    layer_mma<4,4>(aHb,aLb,wHb,wLb,wHs,wLs,g_WH+OW3,g_WL+OW3,acc);
#pragma unroll
    for(int nt=0;nt<4;++nt){
        int c=ngrp*32+nt*8+(lane&3)*2;
        float2 bb=*(const float2*)(b3+c);
        hb[rl*68+c]  =gelu(acc[nt*4+0]+bb.x); hb[rl*68+c+1]  =gelu(acc[nt*4+1]+bb.y);
        hb[(rl+8)*68+c]=gelu(acc[nt*4+2]+bb.x); hb[(rl+8)*68+c+1]=gelu(acc[nt*4+3]+bb.y);
    }
    __syncthreads();
    // L4
    if(tid<BM){ int p=p0+tid;
        if(p<P){ float s=__ldg(b4);
#pragma unroll
            for(int k=0;k<64;++k) s=fmaf(__ldg(W4+k),hb[tid*68+k],s);
            g_E[p]=s; } }
}

// ---- kernel 3: per-row stats + margin flag ---------------------------------
__global__ void rowstats(int B){
    int r=blockIdx.x*blockDim.x+threadIdx.x; if(r>=B) return;
    float e[CAND];
#pragma unroll
    for(int i=0;i<CAND;++i) e[i]=g_E[r*CAND+i];
    float l0=-e[0]*TEMP_INV, mx=l0;
#pragma unroll
    for(int i=1;i<CAND;++i) mx=fmaxf(mx,-e[i]*TEMP_INV);
    float s=0.f;
#pragma unroll
    for(int i=0;i<CAND;++i) s+=expf(-e[i]*TEMP_INV-mx);
    float negs=0.f;
#pragma unroll
    for(int i=1;i<CAND;++i) negs+=e[i];
    float mn=e[1];
#pragma unroll
    for(int i=2;i<CAND;++i) mn=fminf(mn,e[i]);
    g_row[0*BMAX+r]=mx+logf(s)-l0;
    g_row[1*BMAX+r]=e[0];
    g_row[2*BMAX+r]=negs;
    g_row[3*BMAX+r]=(e[0]<=mn)?1.f:0.f;
    if(fabsf(e[0]-mn)<TAU){ int idx=atomicAdd(&g_nflag,1); if(idx<FCAP) g_flags[idx]=r; }
}

// ---- kernel 4: exact fp32 recompute of flagged rows' accuracy bit ----------
__global__ __launch_bounds__(256) void fixup(const float* __restrict__ anchor,
    const float* __restrict__ pos,const float* __restrict__ neg,
    const float* __restrict__ W1,const float* __restrict__ b1,
    const float* __restrict__ W2,const float* __restrict__ b2,
    const float* __restrict__ W3,const float* __restrict__ b3,
    const float* __restrict__ W4,const float* __restrict__ b4){
    __shared__ float h1[256], h2[128], h3[64], ec[CAND];
    int nf=g_nflag; if(nf>FCAP)nf=FCAP;
    for(int f=blockIdx.x; f<nf; f+=gridDim.x){
        int r=g_flags[f];
        const float* x=anchor+(size_t)r*D;
        for(int c=0;c<CAND;++c){
            const float* y=(c==0)? pos+(size_t)r*D : neg+((size_t)r*NNEG+c-1)*D;
            int j=threadIdx.x;
            {   float s=__ldg(b1+j); const float* wr=W1+j*512;
                for(int k=0;k<256;++k) s=fmaf(__ldg(wr+k),__ldg(x+k),s);
                for(int k=0;k<256;++k) s=fmaf(__ldg(wr+256+k),__ldg(y+k),s);
                h1[j]=gelu(s); }
            __syncthreads();
            if(j<128){ float s=__ldg(b2+j); const float* wr=W2+j*256;
                for(int k=0;k<256;++k) s=fmaf(__ldg(wr+k),h1[k],s); h2[j]=gelu(s); }
            __syncthreads();
            if(j<64){ float s=__ldg(b3+j); const float* wr=W3+j*128;
                for(int k=0;k<128;++k) s=fmaf(__ldg(wr+k),h2[k],s); h3[j]=gelu(s); }
            __syncthreads();
            if(j<32){ float s=0.f;
                for(int k=j;k<64;k+=32) s=fmaf(__ldg(W4+k),h3[k],s);
                for(int o=16;o;o>>=1) s+=__shfl_xor_sync(0xFFFFFFFFu,s,o);
                if(j==0) ec[c]=s+__ldg(b4); }
            __syncthreads();
        }
        if(threadIdx.x==0){ float mn=ec[1];
            for(int i=2;i<CAND;++i) mn=fminf(mn,ec[i]);
            g_row[3*BMAX+r]=(ec[0]<=mn)?1.f:0.f; }
        __syncthreads();
    }
}

// ---- kernel 5: deterministic reduction -------------------------------------
__global__ void reduce_k(float* __restrict__ out,int B){
    __shared__ float sred[1024];
    const int tid=threadIdx.x; float tot[4];
    for(int v=0;v<4;++v){
        float s=0.f;
        for(int i=tid;i<B;i+=1024) s+=g_row[v*BMAX+i];
        sred[tid]=s; __syncthreads();
        for(int o=512;o>0;o>>=1){ if(tid<o) sred[tid]+=sred[tid+o]; __syncthreads(); }
        tot[v]=sred[0]; __syncthreads();
    }
    if(tid==0){ float fB=(float)B;
        out[0]=tot[0]/fB; out[1]=tot[1]/fB; out[2]=tot[2]/(fB*NNEG); out[3]=tot[3]/fB; }
}

// ---------------------------------------------------------------------------
extern "C" void kernel_launch(void* const* d_in, const int* in_sizes, int n_in,
                              void* d_out, int out_size){
    const float* anchor=(const float*)d_in[0];
    const float* pos   =(const float*)d_in[1];
    const float* neg   =(const float*)d_in[2];
    const float* W1=(const float*)d_in[3]; const float* b1=(const float*)d_in[4];
    const float* W2=(const float*)d_in[5]; const float* b2=(const float*)d_in[6];
    const float* W3=(const float*)d_in[7]; const float* b3=(const float*)d_in[8];
    const float* W4=(const float*)d_in[9]; const float* b4=(const float*)d_in[10];
    float* out=(float*)d_out;
    int B=in_sizes[0]/D; if(B>BMAX)B=BMAX;
    const int P=B*CAND;
    const int smemB=(BM*AST*2 + 256*WST*2)*4 + BM*68*4;   // 210944 B
    cudaFuncSetAttribute(anchor_tc,cudaFuncAttributeMaxDynamicSharedMemorySize,smemB);
    cudaFuncSetAttribute(mlp_tc,   cudaFuncAttributeMaxDynamicSharedMemorySize,smemB);
    prep_w<<<(WTOT+255)/256,256>>>(W1,W2,W3);
    anchor_tc<<<(B+BM-1)/BM,TPB,smemB>>>(anchor,b1,B);
    mlp_tc<<<(P+BM-1)/BM,TPB,smemB>>>(pos,neg,b2,b3,W4,b4,B);
    rowstats<<<(B+255)/256,256>>>(B);
    fixup<<<128,256>>>(anchor,pos,neg,W1,b1,W2,b2,W3,b3,W4,b4);
    reduce_k<<<1,1024>>>(out,B);
}

// round 12
// speedup vs baseline: 1.9776x; 1.9776x over previous
#include <cuda_runtime.h>

// ---------------------------------------------------------------------------
// ContrastiveEnergyLearning — fused fp32 MLP energy + InfoNCE stats
// R11: 8-row-per-thread blocking (BM=128) halves B-operand LDS traffic per
//      FMA -> crossbar no longer binding; KT=64 halves barrier count.
//      (tcgen05 unavailable: harness targets sm_103 without 'a'; legacy HMMA
//       measured 10x slower than FFMA2 in R8.)
// ---------------------------------------------------------------------------

#define D     256
#define H1    256
#define H2    128
#define H3    64
#define BMAX  32768
#define NNEG  16
#define CAND  17
#define TEMP_INV (1.0f / 0.07f)

#define BM   128    // pairs per block
#define TPB  256
#define PAD  260    // activation buffer row stride (floats)
#define KT   64     // K-chunk for weight staging

typedef unsigned long long u64t;

__device__ float g_A[BMAX * H1];       // anchor-part preactivations (incl. b1)
__device__ float g_W1xT[D * H1];       // W1[:, :256]^T   [k][j]
__device__ float g_W1yT[D * H1];       // W1[:, 256:]^T   [k][j]
__device__ float g_W2T[H1 * H2];       // W2^T            [k][j]
__device__ float g_W3T[H2 * H3];       // W3^T            [k][j]
__device__ float g_E[BMAX * CAND];     // energies
__device__ float g_row[4 * BMAX];      // per-row stats (SoA)

__device__ __forceinline__ float gelu_exact(float x) {
    return 0.5f * x * (1.0f + erff(x * 0.70710678118654752f));
}

__device__ __forceinline__ u64t pack_dup(float x) {
    u64t r; unsigned u = __float_as_uint(x);
    asm("mov.b64 %0, {%1, %1};" : "=l"(r) : "r"(u));
    return r;
}
__device__ __forceinline__ void unpack2(u64t p, float& lo, float& hi) {
    unsigned a, b;
    asm("mov.b64 {%0, %1}, %2;" : "=r"(a), "=r"(b) : "l"(p));
    lo = __uint_as_float(a); hi = __uint_as_float(b);
}
#define FFMA2(d, a, b) \
    asm("fma.rn.f32x2 %0, %1, %2, %0;" : "+l"(d) : "l"(a), "l"(b))

// Register-blocked tile GEMM, packed f32x2, conflict-free float4 n-interleave.
// Thread map: tx = tid&15 owns cols {64v + 4tx + c}; ty = tid>>4 owns rows
// [ty*8, ty*8+8). acc[mm*NF + 4v + c] = col (64v+4tx+c), row ty*8+mm.
template <int N, int K>
__device__ __forceinline__ void gemm_tile(const float* __restrict__ buf,
                                          float* __restrict__ sW,
                                          const float* __restrict__ wT,
                                          float* __restrict__ acc) {
    constexpr int NG = N / 64;
    constexpr int NF = 4 * NG;
    constexpr int NP = 2 * NG;
    const int tid = threadIdx.x;
    const int tx = tid & 15;
    const int ty = tid >> 4;

    u64t accp[8 * NP];
#pragma unroll
    for (int i = 0; i < 8 * NP; ++i) accp[i] = 0ull;

    for (int k0 = 0; k0 < K; k0 += KT) {
        __syncthreads();  // prior sW reads / buf writes complete
        const float4* src = reinterpret_cast<const float4*>(wT + k0 * N);
#pragma unroll
        for (int i = tid; i < KT * N / 4; i += TPB)
            reinterpret_cast<float4*>(sW)[i] = __ldg(src + i);
        __syncthreads();
#pragma unroll
        for (int kk4 = 0; kk4 < KT; kk4 += 4) {
            float4 a4[8];
#pragma unroll
            for (int mm = 0; mm < 8; ++mm)
                a4[mm] = *reinterpret_cast<const float4*>(
                    &buf[(ty * 8 + mm) * PAD + k0 + kk4]);
#pragma unroll
            for (int u = 0; u < 4; ++u) {
                u64t b2[NP];
#pragma unroll
                for (int v = 0; v < NG; ++v) {
                    float4 t = *reinterpret_cast<const float4*>(
                        &sW[(kk4 + u) * N + v * 64 + 4 * tx]);
                    u64t lo, hi;
                    asm("mov.b64 %0, {%1, %2};" : "=l"(lo)
                        : "r"(__float_as_uint(t.x)), "r"(__float_as_uint(t.y)));
                    asm("mov.b64 %0, {%1, %2};" : "=l"(hi)
                        : "r"(__float_as_uint(t.z)), "r"(__float_as_uint(t.w)));
                    b2[2 * v]     = lo;
                    b2[2 * v + 1] = hi;
                }
#pragma unroll
                for (int mm = 0; mm < 8; ++mm) {
                    const u64t a2 =
                        pack_dup(reinterpret_cast<const float*>(&a4[mm])[u]);
#pragma unroll
                    for (int p = 0; p < NP; ++p)
                        FFMA2(accp[mm * NP + p], a2, b2[p]);
                }
            }
        }
    }
    __syncthreads();  // all buf reads done; caller may overwrite buf
#pragma unroll
    for (int mm = 0; mm < 8; ++mm)
#pragma unroll
        for (int p = 0; p < NP; ++p)
            unpack2(accp[mm * NP + p],
                    acc[mm * NF + 2 * p], acc[mm * NF + 2 * p + 1]);
}

// ---- kernel 0: weight transposes (coalesced writes) ------------------------
__global__ void prep_weights(const float* __restrict__ W1,
                             const float* __restrict__ W2,
                             const float* __restrict__ W3) {
    int i = blockIdx.x * blockDim.x + threadIdx.x;
    if (i < D * H1) {
        int k = i >> 8, j = i & 255;
        g_W1xT[i] = W1[j * 512 + k];
        g_W1yT[i] = W1[j * 512 + 256 + k];
    }
    if (i < H1 * H2) {
        int k = i >> 7, j = i & 127;
        g_W2T[i] = W2[j * 256 + k];
    }
    if (i < H2 * H3) {
        int k = i >> 6, j = i & 63;
        g_W3T[i] = W3[j * 128 + k];
    }
}

// ---- kernel 1: A = anchor @ W1x^T + b1  ------------------------------------
__global__ __launch_bounds__(TPB, 1) void anchor_kernel(
    const float* __restrict__ anchor, const float* __restrict__ b1, int B) {
    extern __shared__ float smem[];
    float* buf = smem;
    float* sW  = smem + BM * PAD;
    const int tid = threadIdx.x;
    const int r0 = blockIdx.x * BM;

    for (int i = tid; i < BM * (D / 4); i += TPB) {
        int m = i >> 6, q = i & 63;
        int r = r0 + m; if (r >= B) r = B - 1;
        *reinterpret_cast<float4*>(&buf[m * PAD + q * 4]) =
            __ldg(reinterpret_cast<const float4*>(anchor + (size_t)r * D) + q);
    }

    constexpr int NG = H1 / 64;
    constexpr int NF = 4 * NG;
    float acc[8 * NF];
    gemm_tile<H1, D>(buf, sW, g_W1xT, acc);

    const int tx = tid & 15, ty = tid >> 4;
#pragma unroll
    for (int mm = 0; mm < 8; ++mm) {
        int r = r0 + ty * 8 + mm;
        if (r < B) {
#pragma unroll
            for (int v = 0; v < NG; ++v) {
                int j = v * 64 + 4 * tx;
                float4 bb = __ldg(reinterpret_cast<const float4*>(b1 + j));
                float4 o;
                o.x = acc[mm * NF + 4 * v + 0] + bb.x;
                o.y = acc[mm * NF + 4 * v + 1] + bb.y;
                o.z = acc[mm * NF + 4 * v + 2] + bb.z;
                o.w = acc[mm * NF + 4 * v + 3] + bb.w;
                *reinterpret_cast<float4*>(&g_A[(size_t)r * H1 + j]) = o;
            }
        }
    }
}

// ---- kernel 2: fused 4-layer MLP per 128-pair tile -------------------------
__global__ __launch_bounds__(TPB, 1) void mlp_kernel(
    const float* __restrict__ positive, const float* __restrict__ negatives,
    const float* __restrict__ b2, const float* __restrict__ b3,
    const float* __restrict__ W4, const float* __restrict__ b4, int B) {
    extern __shared__ float smem[];
    float* buf = smem;              // [BM][PAD] activation buffer (reused)
    float* sW  = smem + BM * PAD;   // [KT][256] weight staging
    const int tid = threadIdx.x;
    const int tx = tid & 15, ty = tid >> 4;
    const int P = B * CAND;
    const int p0 = blockIdx.x * BM;

    // Load Y tile (positive for c==0, negatives otherwise)
    for (int i = tid; i < BM * (D / 4); i += TPB) {
        int m = i >> 6, q = i & 63;
        int p = p0 + m; if (p >= P) p = P - 1;
        int r = p / CAND, c = p - r * CAND;
        const float* y = (c == 0) ? (positive + (size_t)r * D)
                                  : (negatives + ((size_t)r * NNEG + (c - 1)) * D);
        *reinterpret_cast<float4*>(&buf[m * PAD + q * 4]) =
            __ldg(reinterpret_cast<const float4*>(y) + q);
    }

    {   // layer 1: h1 = gelu(Y @ W1y^T + A[row])
        constexpr int NG = H1 / 64;
        constexpr int NF = 4 * NG;
        float acc[8 * NF];
        gemm_tile<H1, D>(buf, sW, g_W1yT, acc);
#pragma unroll
        for (int mm = 0; mm < 8; ++mm) {
            int m = ty * 8 + mm;
            int p = p0 + m; if (p >= P) p = P - 1;
            int r = p / CAND;
#pragma unroll
            for (int v = 0; v < NG; ++v) {
                int j = v * 64 + 4 * tx;
                float4 av = __ldg(reinterpret_cast<const float4*>(&g_A[(size_t)r * H1 + j]));
                buf[m * PAD + j + 0] = gelu_exact(acc[mm * NF + 4 * v + 0] + av.x);
                buf[m * PAD + j + 1] = gelu_exact(acc[mm * NF + 4 * v + 1] + av.y);
                buf[m * PAD + j + 2] = gelu_exact(acc[mm * NF + 4 * v + 2] + av.z);
                buf[m * PAD + j + 3] = gelu_exact(acc[mm * NF + 4 * v + 3] + av.w);
            }
        }
    }
    {   // layer 2: h2 = gelu(h1 @ W2^T + b2)
        constexpr int NG = H2 / 64;
        constexpr int NF = 4 * NG;
        float acc[8 * NF];
        gemm_tile<H2, H1>(buf, sW, g_W2T, acc);
#pragma unroll
        for (int mm = 0; mm < 8; ++mm) {
            int m = ty * 8 + mm;
#pragma unroll
            for (int v = 0; v < NG; ++v) {
                int j = v * 64 + 4 * tx;
                float4 bb = __ldg(reinterpret_cast<const float4*>(b2 + j));
                buf[m * PAD + j + 0] = gelu_exact(acc[mm * NF + 4 * v + 0] + bb.x);
                buf[m * PAD + j + 1] = gelu_exact(acc[mm * NF + 4 * v + 1] + bb.y);
                buf[m * PAD + j + 2] = gelu_exact(acc[mm * NF + 4 * v + 2] + bb.z);
                buf[m * PAD + j + 3] = gelu_exact(acc[mm * NF + 4 * v + 3] + bb.w);
            }
        }
    }
    {   // layer 3: h3 = gelu(h2 @ W3^T + b3)
        constexpr int NG = H3 / 64;
        constexpr int NF = 4 * NG;
        float acc[8 * NF];
        gemm_tile<H3, H2>(buf, sW, g_W3T, acc);
#pragma unroll
        for (int mm = 0; mm < 8; ++mm) {
            int m = ty * 8 + mm;
#pragma unroll
            for (int v = 0; v < NG; ++v) {
                int j = v * 64 + 4 * tx;
                float4 bb = __ldg(reinterpret_cast<const float4*>(b3 + j));
                buf[m * PAD + j + 0] = gelu_exact(acc[mm * NF + 4 * v + 0] + bb.x);
                buf[m * PAD + j + 1] = gelu_exact(acc[mm * NF + 4 * v + 1] + bb.y);
                buf[m * PAD + j + 2] = gelu_exact(acc[mm * NF + 4 * v + 2] + bb.z);
                buf[m * PAD + j + 3] = gelu_exact(acc[mm * NF + 4 * v + 3] + bb.w);
            }
        }
    }
    // layer 4: e = h3 . W4 + b4 (one thread per pair)
    __syncthreads();
    if (tid < BM) {
        int p = p0 + tid;
        if (p < P) {
            float s = __ldg(b4);
#pragma unroll
            for (int k = 0; k < H3; ++k)
                s = fmaf(__ldg(W4 + k), buf[tid * PAD + k], s);
            g_E[p] = s;
        }
    }
}

// ---- kernel 3: per-row softmax/loss/argmin stats ---------------------------
__global__ void rowstats_kernel(int B) {
    int r = blockIdx.x * blockDim.x + threadIdx.x;
    if (r >= B) return;
    float e[CAND];
#pragma unroll
    for (int i = 0; i < CAND; ++i) e[i] = g_E[r * CAND + i];

    float l0 = -e[0] * TEMP_INV;
    float mx = l0;
#pragma unroll
    for (int i = 1; i < CAND; ++i) mx = fmaxf(mx, -e[i] * TEMP_INV);
    float s = 0.0f;
#pragma unroll
    for (int i = 0; i < CAND; ++i) s += expf(-e[i] * TEMP_INV - mx);
    float lse = mx + logf(s);

    float negs = 0.0f;
#pragma unroll
    for (int i = 1; i < CAND; ++i) negs += e[i];

    int am = 0; float best = e[0];
#pragma unroll
    for (int i = 1; i < CAND; ++i)
        if (e[i] < best) { best = e[i]; am = i; }

    g_row[0 * BMAX + r] = lse - l0;
    g_row[1 * BMAX + r] = e[0];
    g_row[2 * BMAX + r] = negs;
    g_row[3 * BMAX + r] = (am == 0) ? 1.0f : 0.0f;
}

// ---- kernel 4: deterministic single-block reduction ------------------------
__global__ void reduce_kernel(float* __restrict__ out, int B) {
    __shared__ float sred[1024];
    const int tid = threadIdx.x;
    float totals[4];
    for (int v = 0; v < 4; ++v) {
        float s = 0.0f;
        for (int i = tid; i < B; i += 1024) s += g_row[v * BMAX + i];
        sred[tid] = s;
        __syncthreads();
        for (int off = 512; off > 0; off >>= 1) {
            if (tid < off) sred[tid] += sred[tid + off];
            __syncthreads();
        }
        totals[v] = sred[0];
        __syncthreads();
    }
    if (tid == 0) {
        const float fB = (float)B;
        out[0] = totals[0] / fB;             // loss
        out[1] = totals[1] / fB;             // pos_energy
        out[2] = totals[2] / (fB * NNEG);    // neg_energy
        out[3] = totals[3] / fB;             // accuracy
    }
}

// ---------------------------------------------------------------------------
extern "C" void kernel_launch(void* const* d_in, const int* in_sizes, int n_in,
                              void* d_out, int out_size) {
    const float* anchor    = (const float*)d_in[0];
    const float* positive  = (const float*)d_in[1];
    const float* negatives = (const float*)d_in[2];
    const float* W1        = (const float*)d_in[3];
    const float* b1        = (const float*)d_in[4];
    const float* W2        = (const float*)d_in[5];
    const float* b2        = (const float*)d_in[6];
    const float* W3        = (const float*)d_in[7];
    const float* b3        = (const float*)d_in[8];
    const float* W4        = (const float*)d_in[9];
    const float* b4        = (const float*)d_in[10];
    float* out = (float*)d_out;

    int B = in_sizes[0] / D;
    if (B > BMAX) B = BMAX;
    const int P = B * CAND;

    const int smem = (BM * PAD + KT * 256) * (int)sizeof(float);  // 198656 B
    cudaFuncSetAttribute(anchor_kernel, cudaFuncAttributeMaxDynamicSharedMemorySize, smem);
    cudaFuncSetAttribute(mlp_kernel,    cudaFuncAttributeMaxDynamicSharedMemorySize, smem);

    prep_weights<<<(D * H1 + 255) / 256, 256>>>(W1, W2, W3);
    anchor_kernel<<<(B + BM - 1) / BM, TPB, smem>>>(anchor, b1, B);
    mlp_kernel<<<(P + BM - 1) / BM, TPB, smem>>>(positive, negatives, b2, b3, W4, b4, B);
    rowstats_kernel<<<(B + 255) / 256, 256>>>(B);
    reduce_kernel<<<1, 1024>>>(out, B);
}

// round 13
// speedup vs baseline: 2.3595x; 1.1931x over previous
#include <cuda_runtime.h>

// ---------------------------------------------------------------------------
// ContrastiveEnergyLearning — fused fp32 MLP energy + InfoNCE stats
// R12: R4 skeleton (BM=64, 2 CTAs/SM, conflict-free f32x2 GEMM) +
//      fast rational erf, L4 folded into L3 epilogue via shfl, hoisted biases.
// ---------------------------------------------------------------------------

#define D     256
#define H1    256
#define H2    128
#define H3    64
#define BMAX  32768
#define NNEG  16
#define CAND  17
#define TEMP_INV (1.0f / 0.07f)

#define BM   64     // pairs per block
#define TPB  256
#define PAD  260    // activation buffer row stride (floats)
#define KT   32     // K-chunk for weight staging

typedef unsigned long long u64t;

__device__ float g_A[BMAX * H1];       // anchor-part preactivations (incl. b1)
__device__ float g_W1xT[D * H1];       // W1[:, :256]^T   [k][j]
__device__ float g_W1yT[D * H1];       // W1[:, 256:]^T   [k][j]
__device__ float g_W2T[H1 * H2];       // W2^T            [k][j]
__device__ float g_W3T[H2 * H3];       // W3^T            [k][j]
__device__ float g_E[BMAX * CAND];     // energies
__device__ float g_row[4 * BMAX];      // per-row stats (SoA)

// Fast erf-GELU: Abramowitz–Stegun 7.1.26 (|eps| <= 1.5e-7) + fast rcp/exp.
__device__ __forceinline__ float gelu_exact(float x) {
    float z = fabsf(x) * 0.70710678118654752f;
    float t = __fdividef(1.0f, fmaf(0.3275911f, z, 1.0f));
    float p = t * fmaf(t, fmaf(t, fmaf(t, fmaf(t, 1.061405429f, -1.453152027f),
                                       1.421413741f), -0.284496736f), 0.254829592f);
    float e = __expf(-z * z);
    float erfv = copysignf(fmaf(-p, e, 1.0f), x);
    return 0.5f * x * (1.0f + erfv);
}

__device__ __forceinline__ u64t pack_dup(float x) {
    u64t r; unsigned u = __float_as_uint(x);
    asm("mov.b64 %0, {%1, %1};" : "=l"(r) : "r"(u));
    return r;
}
__device__ __forceinline__ void unpack2(u64t p, float& lo, float& hi) {
    unsigned a, b;
    asm("mov.b64 {%0, %1}, %2;" : "=r"(a), "=r"(b) : "l"(p));
    lo = __uint_as_float(a); hi = __uint_as_float(b);
}
#define FFMA2(d, a, b) \
    asm("fma.rn.f32x2 %0, %1, %2, %0;" : "+l"(d) : "l"(a), "l"(b))

// Register-blocked tile GEMM, packed f32x2, conflict-free float4 n-interleave.
// Thread map: tx = tid&15 owns cols {64v + 4tx + c}; ty = tid>>4 owns rows
// [ty*4, ty*4+4). acc[mm*NF + 4v + c] = col (64v+4tx+c), row ty*4+mm.
template <int N, int K>
__device__ __forceinline__ void gemm_tile(const float* __restrict__ buf,
                                          float* __restrict__ sW,
                                          const float* __restrict__ wT,
                                          float* __restrict__ acc) {
    constexpr int NG = N / 64;
    constexpr int NF = 4 * NG;
    constexpr int NP = 2 * NG;
    const int tid = threadIdx.x;
    const int tx = tid & 15;
    const int ty = tid >> 4;

    u64t accp[4 * NP];
#pragma unroll
    for (int i = 0; i < 4 * NP; ++i) accp[i] = 0ull;

    for (int k0 = 0; k0 < K; k0 += KT) {
        __syncthreads();  // prior sW reads / buf writes complete
        const float4* src = reinterpret_cast<const float4*>(wT + k0 * N);
#pragma unroll
        for (int i = tid; i < KT * N / 4; i += TPB)
            reinterpret_cast<float4*>(sW)[i] = __ldg(src + i);
        __syncthreads();
#pragma unroll
        for (int kk4 = 0; kk4 < KT; kk4 += 4) {
            float4 a4[4];
#pragma unroll
            for (int mm = 0; mm < 4; ++mm)
                a4[mm] = *reinterpret_cast<const float4*>(
                    &buf[(ty * 4 + mm) * PAD + k0 + kk4]);
#pragma unroll
            for (int u = 0; u < 4; ++u) {
                u64t b2[NP];
#pragma unroll
                for (int v = 0; v < NG; ++v) {
                    float4 t = *reinterpret_cast<const float4*>(
                        &sW[(kk4 + u) * N + v * 64 + 4 * tx]);
                    u64t lo, hi;
                    asm("mov.b64 %0, {%1, %2};" : "=l"(lo)
                        : "r"(__float_as_uint(t.x)), "r"(__float_as_uint(t.y)));
                    asm("mov.b64 %0, {%1, %2};" : "=l"(hi)
                        : "r"(__float_as_uint(t.z)), "r"(__float_as_uint(t.w)));
                    b2[2 * v]     = lo;
                    b2[2 * v + 1] = hi;
                }
#pragma unroll
                for (int mm = 0; mm < 4; ++mm) {
                    const u64t a2 =
                        pack_dup(reinterpret_cast<const float*>(&a4[mm])[u]);
#pragma unroll
                    for (int p = 0; p < NP; ++p)
                        FFMA2(accp[mm * NP + p], a2, b2[p]);
                }
            }
        }
    }
    __syncthreads();  // all buf reads done; caller may overwrite buf
#pragma unroll
    for (int mm = 0; mm < 4; ++mm)
#pragma unroll
        for (int p = 0; p < NP; ++p)
            unpack2(accp[mm * NP + p],
                    acc[mm * NF + 2 * p], acc[mm * NF + 2 * p + 1]);
}

// ---- kernel 0: weight transposes (coalesced writes) ------------------------
__global__ void prep_weights(const float* __restrict__ W1,
                             const float* __restrict__ W2,
                             const float* __restrict__ W3) {
    int i = blockIdx.x * blockDim.x + threadIdx.x;
    if (i < D * H1) {
        int k = i >> 8, j = i & 255;
        g_W1xT[i] = W1[j * 512 + k];
        g_W1yT[i] = W1[j * 512 + 256 + k];
    }
    if (i < H1 * H2) {
        int k = i >> 7, j = i & 127;
        g_W2T[i] = W2[j * 256 + k];
    }
    if (i < H2 * H3) {
        int k = i >> 6, j = i & 63;
        g_W3T[i] = W3[j * 128 + k];
    }
}

// ---- kernel 1: A = anchor @ W1x^T + b1  ------------------------------------
__global__ __launch_bounds__(TPB, 2) void anchor_kernel(
    const float* __restrict__ anchor, const float* __restrict__ b1, int B) {
    extern __shared__ float smem[];
    float* buf = smem;
    float* sW  = smem + BM * PAD;
    const int tid = threadIdx.x;
    const int r0 = blockIdx.x * BM;

    for (int i = tid; i < BM * (D / 4); i += TPB) {
        int m = i >> 6, q = i & 63;
        int r = r0 + m; if (r >= B) r = B - 1;
        *reinterpret_cast<float4*>(&buf[m * PAD + q * 4]) =
            __ldg(reinterpret_cast<const float4*>(anchor + (size_t)r * D) + q);
    }

    constexpr int NG = H1 / 64;
    constexpr int NF = 4 * NG;
    float acc[4 * NF];
    gemm_tile<H1, D>(buf, sW, g_W1xT, acc);

    const int tx = tid & 15, ty = tid >> 4;
#pragma unroll
    for (int v = 0; v < NG; ++v) {
        int j = v * 64 + 4 * tx;
        float4 bb = __ldg(reinterpret_cast<const float4*>(b1 + j));
#pragma unroll
        for (int mm = 0; mm < 4; ++mm) {
            int r = r0 + ty * 4 + mm;
            if (r < B) {
                float4 o;
                o.x = acc[mm * NF + 4 * v + 0] + bb.x;
                o.y = acc[mm * NF + 4 * v + 1] + bb.y;
                o.z = acc[mm * NF + 4 * v + 2] + bb.z;
                o.w = acc[mm * NF + 4 * v + 3] + bb.w;
                *reinterpret_cast<float4*>(&g_A[(size_t)r * H1 + j]) = o;
            }
        }
    }
}

// ---- kernel 2: fused 4-layer MLP per 64-pair tile --------------------------
__global__ __launch_bounds__(TPB, 2) void mlp_kernel(
    const float* __restrict__ positive, const float* __restrict__ negatives,
    const float* __restrict__ b2, const float* __restrict__ b3,
    const float* __restrict__ W4, const float* __restrict__ b4, int B) {
    extern __shared__ float smem[];
    float* buf = smem;              // [BM][PAD] activation buffer (reused)
    float* sW  = smem + BM * PAD;   // [KT][256] weight staging
    const int tid = threadIdx.x;
    const int tx = tid & 15, ty = tid >> 4;
    const int P = B * CAND;
    const int p0 = blockIdx.x * BM;

    // Load Y tile (positive for c==0, negatives otherwise)
    for (int i = tid; i < BM * (D / 4); i += TPB) {
        int m = i >> 6, q = i & 63;
        int p = p0 + m; if (p >= P) p = P - 1;
        int r = p / CAND, c = p - r * CAND;
        const float* y = (c == 0) ? (positive + (size_t)r * D)
                                  : (negatives + ((size_t)r * NNEG + (c - 1)) * D);
        *reinterpret_cast<float4*>(&buf[m * PAD + q * 4]) =
            __ldg(reinterpret_cast<const float4*>(y) + q);
    }

    {   // layer 1: h1 = gelu(Y @ W1y^T + A[row])
        constexpr int NG = H1 / 64;
        constexpr int NF = 4 * NG;
        float acc[4 * NF];
        gemm_tile<H1, D>(buf, sW, g_W1yT, acc);
#pragma unroll
        for (int mm = 0; mm < 4; ++mm) {
            int m = ty * 4 + mm;
            int p = p0 + m; if (p >= P) p = P - 1;
            int r = p / CAND;
#pragma unroll
            for (int v = 0; v < NG; ++v) {
                int j = v * 64 + 4 * tx;
                float4 av = __ldg(reinterpret_cast<const float4*>(&g_A[(size_t)r * H1 + j]));
                buf[m * PAD + j + 0] = gelu_exact(acc[mm * NF + 4 * v + 0] + av.x);
                buf[m * PAD + j + 1] = gelu_exact(acc[mm * NF + 4 * v + 1] + av.y);
                buf[m * PAD + j + 2] = gelu_exact(acc[mm * NF + 4 * v + 2] + av.z);
                buf[m * PAD + j + 3] = gelu_exact(acc[mm * NF + 4 * v + 3] + av.w);
            }
        }
    }
    {   // layer 2: h2 = gelu(h1 @ W2^T + b2)
        constexpr int NG = H2 / 64;
        constexpr int NF = 4 * NG;
        float acc[4 * NF];
        gemm_tile<H2, H1>(buf, sW, g_W2T, acc);
#pragma unroll
        for (int v = 0; v < NG; ++v) {
            int j = v * 64 + 4 * tx;
            float4 bb = __ldg(reinterpret_cast<const float4*>(b2 + j));
#pragma unroll
            for (int mm = 0; mm < 4; ++mm) {
                int m = ty * 4 + mm;
                buf[m * PAD + j + 0] = gelu_exact(acc[mm * NF + 4 * v + 0] + bb.x);
                buf[m * PAD + j + 1] = gelu_exact(acc[mm * NF + 4 * v + 1] + bb.y);
                buf[m * PAD + j + 2] = gelu_exact(acc[mm * NF + 4 * v + 2] + bb.z);
                buf[m * PAD + j + 3] = gelu_exact(acc[mm * NF + 4 * v + 3] + bb.w);
            }
        }
    }
    {   // layer 3 + layer 4 fused: e = gelu(h2 @ W3^T + b3) . W4 + b4
        // N=64, NG=1: thread owns cols {4tx..4tx+3}, rows ty*4+mm.
        // Per-row partial dot reduced across tx via shfl_xor (tx = lane low 4 bits).
        float acc[4 * 4];
        gemm_tile<H3, H2>(buf, sW, g_W3T, acc);
        int j = 4 * tx;
        float4 bb = __ldg(reinterpret_cast<const float4*>(b3 + j));
        float4 w4 = __ldg(reinterpret_cast<const float4*>(W4 + j));
        float b4v = __ldg(b4);
#pragma unroll
        for (int mm = 0; mm < 4; ++mm) {
            float s;
            s  = gelu_exact(acc[mm * 4 + 0] + bb.x) * w4.x;
            s += gelu_exact(acc[mm * 4 + 1] + bb.y) * w4.y;
            s += gelu_exact(acc[mm * 4 + 2] + bb.z) * w4.z;
            s += gelu_exact(acc[mm * 4 + 3] + bb.w) * w4.w;
#pragma unroll
            for (int off = 8; off > 0; off >>= 1)
                s += __shfl_xor_sync(0xFFFFFFFFu, s, off);
            if (tx == 0) {
                int p = p0 + ty * 4 + mm;
                if (p < P) g_E[p] = s + b4v;
            }
        }
    }
}

// ---- kernel 3: per-row softmax/loss/argmin stats ---------------------------
__global__ void rowstats_kernel(int B) {
    int r = blockIdx.x * blockDim.x + threadIdx.x;
    if (r >= B) return;
    float e[CAND];
#pragma unroll
    for (int i = 0; i < CAND; ++i) e[i] = g_E[r * CAND + i];

    float l0 = -e[0] * TEMP_INV;
    float mx = l0;
#pragma unroll
    for (int i = 1; i < CAND; ++i) mx = fmaxf(mx, -e[i] * TEMP_INV);
    float s = 0.0f;
#pragma unroll
    for (int i = 0; i < CAND; ++i) s += expf(-e[i] * TEMP_INV - mx);
    float lse = mx + logf(s);

    float negs = 0.0f;
#pragma unroll
    for (int i = 1; i < CAND; ++i) negs += e[i];

    int am = 0; float best = e[0];
#pragma unroll
    for (int i = 1; i < CAND; ++i)
        if (e[i] < best) { best = e[i]; am = i; }

    g_row[0 * BMAX + r] = lse - l0;
    g_row[1 * BMAX + r] = e[0];
    g_row[2 * BMAX + r] = negs;
    g_row[3 * BMAX + r] = (am == 0) ? 1.0f : 0.0f;
}

// ---- kernel 4: deterministic single-block reduction ------------------------
__global__ void reduce_kernel(float* __restrict__ out, int B) {
    __shared__ float sred[1024];
    const int tid = threadIdx.x;
    float totals[4];
    for (int v = 0; v < 4; ++v) {
        float s = 0.0f;
        for (int i = tid; i < B; i += 1024) s += g_row[v * BMAX + i];
        sred[tid] = s;
        __syncthreads();
        for (int off = 512; off > 0; off >>= 1) {
            if (tid < off) sred[tid] += sred[tid + off];
            __syncthreads();
        }
        totals[v] = sred[0];
        __syncthreads();
    }
    if (tid == 0) {
        const float fB = (float)B;
        out[0] = totals[0] / fB;             // loss
        out[1] = totals[1] / fB;             // pos_energy
        out[2] = totals[2] / (fB * NNEG);    // neg_energy
        out[3] = totals[3] / fB;             // accuracy
    }
}

// ---------------------------------------------------------------------------
extern "C" void kernel_launch(void* const* d_in, const int* in_sizes, int n_in,
                              void* d_out, int out_size) {
    const float* anchor    = (const float*)d_in[0];
    const float* positive  = (const float*)d_in[1];
    const float* negatives = (const float*)d_in[2];
    const float* W1        = (const float*)d_in[3];
    const float* b1        = (const float*)d_in[4];
    const float* W2        = (const float*)d_in[5];
    const float* b2        = (const float*)d_in[6];
    const float* W3        = (const float*)d_in[7];
    const float* b3        = (const float*)d_in[8];
    const float* W4        = (const float*)d_in[9];
    const float* b4        = (const float*)d_in[10];
    float* out = (float*)d_out;

    int B = in_sizes[0] / D;
    if (B > BMAX) B = BMAX;
    const int P = B * CAND;

    const int smem = (BM * PAD + KT * 256) * (int)sizeof(float);  // 99328 B
    cudaFuncSetAttribute(anchor_kernel, cudaFuncAttributeMaxDynamicSharedMemorySize, smem);
    cudaFuncSetAttribute(mlp_kernel,    cudaFuncAttributeMaxDynamicSharedMemorySize, smem);

    prep_weights<<<(D * H1 + 255) / 256, 256>>>(W1, W2, W3);
    anchor_kernel<<<(B + BM - 1) / BM, TPB, smem>>>(anchor, b1, B);
    mlp_kernel<<<(P + BM - 1) / BM, TPB, smem>>>(positive, negatives, b2, b3, W4, b4, B);
    rowstats_kernel<<<(B + 255) / 256, 256>>>(B);
    reduce_kernel<<<1, 1024>>>(out, B);
}

// round 15
// speedup vs baseline: 2.4818x; 1.0518x over previous
#include <cuda_runtime.h>
#include <cstdint>

// ---------------------------------------------------------------------------
// ContrastiveEnergyLearning — fused fp32 MLP energy + InfoNCE stats
// R13: cp.async double-buffered weight staging (KT=16 ping-pong) hides the
//      ~600-cyc weight-load latency behind compute; GEMM math bitwise-same
//      as R12 (fast erf, fused L3+L4, conflict-free f32x2 core).
// ---------------------------------------------------------------------------

#define D     256
#define H1    256
#define H2    128
#define H3    64
#define BMAX  32768
#define NNEG  16
#define CAND  17
#define TEMP_INV (1.0f / 0.07f)

#define BM   64     // pairs per block
#define TPB  256
#define PAD  260    // activation buffer row stride (floats)
#define KT   16     // K-chunk for weight staging (x2 buffers)

typedef unsigned long long u64t;

__device__ float g_A[BMAX * H1];       // anchor-part preactivations (incl. b1)
__device__ float g_W1xT[D * H1];       // W1[:, :256]^T   [k][j]
__device__ float g_W1yT[D * H1];       // W1[:, 256:]^T   [k][j]
__device__ float g_W2T[H1 * H2];       // W2^T            [k][j]
__device__ float g_W3T[H2 * H3];       // W3^T            [k][j]
__device__ float g_E[BMAX * CAND];     // energies
__device__ float g_row[4 * BMAX];      // per-row stats (SoA)

// Fast erf-GELU: Abramowitz–Stegun 7.1.26 (|eps| <= 1.5e-7) + fast rcp/exp.
__device__ __forceinline__ float gelu_exact(float x) {
    float z = fabsf(x) * 0.70710678118654752f;
    float t = __fdividef(1.0f, fmaf(0.3275911f, z, 1.0f));
    float p = t * fmaf(t, fmaf(t, fmaf(t, fmaf(t, 1.061405429f, -1.453152027f),
                                       1.421413741f), -0.284496736f), 0.254829592f);
    float e = __expf(-z * z);
    float erfv = copysignf(fmaf(-p, e, 1.0f), x);
    return 0.5f * x * (1.0f + erfv);
}

__device__ __forceinline__ uint32_t smem_u32(const void* p) {
    uint32_t a;
    asm("{ .reg .u64 t; cvta.to.shared.u64 t, %1; cvt.u32.u64 %0, t; }"
        : "=r"(a) : "l"(p));
    return a;
}
__device__ __forceinline__ void cpasync16(uint32_t dst, const void* src) {
    asm volatile("cp.async.cg.shared.global [%0], [%1], 16;" :: "r"(dst), "l"(src));
}
#define CP_COMMIT() asm volatile("cp.async.commit_group;" ::: "memory")
#define CP_WAIT1()  asm volatile("cp.async.wait_group 1;" ::: "memory")
#define CP_WAIT0()  asm volatile("cp.async.wait_group 0;" ::: "memory")

__device__ __forceinline__ u64t pack_dup(float x) {
    u64t r; unsigned u = __float_as_uint(x);
    asm("mov.b64 %0, {%1, %1};" : "=l"(r) : "r"(u));
    return r;
}
__device__ __forceinline__ void unpack2(u64t p, float& lo, float& hi) {
    unsigned a, b;
    asm("mov.b64 {%0, %1}, %2;" : "=r"(a), "=r"(b) : "l"(p));
    lo = __uint_as_float(a); hi = __uint_as_float(b);
}
#define FFMA2(d, a, b) \
    asm("fma.rn.f32x2 %0, %1, %2, %0;" : "+l"(d) : "l"(a), "l"(b))

// Register-blocked tile GEMM, packed f32x2, conflict-free float4 n-interleave,
// cp.async double-buffered weight staging.
// Thread map: tx = tid&15 owns cols {64v + 4tx + c}; ty = tid>>4 owns rows
// [ty*4, ty*4+4). acc[mm*NF + 4v + c] = col (64v+4tx+c), row ty*4+mm.
template <int N, int K>
__device__ __forceinline__ void gemm_tile(const float* __restrict__ buf,
                                          float* __restrict__ sW0,
                                          float* __restrict__ sW1,
                                          const float* __restrict__ wT,
                                          float* __restrict__ acc) {
    constexpr int NG  = N / 64;
    constexpr int NF  = 4 * NG;
    constexpr int NP  = 2 * NG;
    constexpr int C   = K / KT;            // chunks
    constexpr int OPS = (KT * N) / 1024;   // 16B cp.async per thread per chunk
    const int tid = threadIdx.x;
    const int tx = tid & 15;
    const int ty = tid >> 4;
    const uint32_t s0 = smem_u32(sW0), s1 = smem_u32(sW1);

    u64t accp[4 * NP];
#pragma unroll
    for (int i = 0; i < 4 * NP; ++i) accp[i] = 0ull;

    {   // stage chunk 0 -> buffer 0
        const char* src = (const char*)wT + tid * 16;
#pragma unroll
        for (int o = 0; o < OPS; ++o)
            cpasync16(s0 + (uint32_t)(tid * 16 + o * 4096), src + o * 4096);
        CP_COMMIT();
    }

    for (int c = 0; c < C; ++c) {
        const float* sWc = (c & 1) ? sW1 : sW0;
        if (c + 1 < C) {   // prefetch next chunk into the other buffer
            uint32_t snx = (c & 1) ? s0 : s1;
            const char* src = (const char*)(wT + (c + 1) * KT * N) + tid * 16;
#pragma unroll
            for (int o = 0; o < OPS; ++o)
                cpasync16(snx + (uint32_t)(tid * 16 + o * 4096), src + o * 4096);
            CP_COMMIT();
            CP_WAIT1();    // chunk c resident; c+1 may still be in flight
        } else {
            CP_WAIT0();
        }
        __syncthreads();   // all threads' copies + prior buf writes visible
        const int k0 = c * KT;
#pragma unroll
        for (int kk4 = 0; kk4 < KT; kk4 += 4) {
            float4 a4[4];
#pragma unroll
            for (int mm = 0; mm < 4; ++mm)
                a4[mm] = *reinterpret_cast<const float4*>(
                    &buf[(ty * 4 + mm) * PAD + k0 + kk4]);
#pragma unroll
            for (int u = 0; u < 4; ++u) {
                u64t b2[NP];
#pragma unroll
                for (int v = 0; v < NG; ++v) {
                    float4 t = *reinterpret_cast<const float4*>(
                        &sWc[(kk4 + u) * N + v * 64 + 4 * tx]);
                    u64t lo, hi;
                    asm("mov.b64 %0, {%1, %2};" : "=l"(lo)
                        : "r"(__float_as_uint(t.x)), "r"(__float_as_uint(t.y)));
                    asm("mov.b64 %0, {%1, %2};" : "=l"(hi)
                        : "r"(__float_as_uint(t.z)), "r"(__float_as_uint(t.w)));
                    b2[2 * v]     = lo;
                    b2[2 * v + 1] = hi;
                }
#pragma unroll
                for (int mm = 0; mm < 4; ++mm) {
                    const u64t a2 =
                        pack_dup(reinterpret_cast<const float*>(&a4[mm])[u]);
#pragma unroll
                    for (int p = 0; p < NP; ++p)
                        FFMA2(accp[mm * NP + p], a2, b2[p]);
                }
            }
        }
        __syncthreads();   // compute(c) reads done before buffer reuse
    }
#pragma unroll
    for (int mm = 0; mm < 4; ++mm)
#pragma unroll
        for (int p = 0; p < NP; ++p)
            unpack2(accp[mm * NP + p],
                    acc[mm * NF + 2 * p], acc[mm * NF + 2 * p + 1]);
}

// ---- kernel 0: weight transposes (coalesced writes) ------------------------
__global__ void prep_weights(const float* __restrict__ W1,
                             const float* __restrict__ W2,
                             const float* __restrict__ W3) {
    int i = blockIdx.x * blockDim.x + threadIdx.x;
    if (i < D * H1) {
        int k = i >> 8, j = i & 255;
        g_W1xT[i] = W1[j * 512 + k];
        g_W1yT[i] = W1[j * 512 + 256 + k];
    }
    if (i < H1 * H2) {
        int k = i >> 7, j = i & 127;
        g_W2T[i] = W2[j * 256 + k];
    }
    if (i < H2 * H3) {
        int k = i >> 6, j = i & 63;
        g_W3T[i] = W3[j * 128 + k];
    }
}

// ---- kernel 1: A = anchor @ W1x^T + b1  ------------------------------------
__global__ __launch_bounds__(TPB, 2) void anchor_kernel(
    const float* __restrict__ anchor, const float* __restrict__ b1, int B) {
    extern __shared__ float smem[];
    float* buf = smem;
    float* sW0 = smem + BM * PAD;
    float* sW1 = sW0 + KT * 256;
    const int tid = threadIdx.x;
    const int r0 = blockIdx.x * BM;

    for (int i = tid; i < BM * (D / 4); i += TPB) {
        int m = i >> 6, q = i & 63;
        int r = r0 + m; if (r >= B) r = B - 1;
        *reinterpret_cast<float4*>(&buf[m * PAD + q * 4]) =
            __ldg(reinterpret_cast<const float4*>(anchor + (size_t)r * D) + q);
    }

    constexpr int NG = H1 / 64;
    constexpr int NF = 4 * NG;
    float acc[4 * NF];
    gemm_tile<H1, D>(buf, sW0, sW1, g_W1xT, acc);

    const int tx = tid & 15, ty = tid >> 4;
#pragma unroll
    for (int v = 0; v < NG; ++v) {
        int j = v * 64 + 4 * tx;
        float4 bb = __ldg(reinterpret_cast<const float4*>(b1 + j));
#pragma unroll
        for (int mm = 0; mm < 4; ++mm) {
            int r = r0 + ty * 4 + mm;
            if (r < B) {
                float4 o;
                o.x = acc[mm * NF + 4 * v + 0] + bb.x;
                o.y = acc[mm * NF + 4 * v + 1] + bb.y;
                o.z = acc[mm * NF + 4 * v + 2] + bb.z;
                o.w = acc[mm * NF + 4 * v + 3] + bb.w;
                *reinterpret_cast<float4*>(&g_A[(size_t)r * H1 + j]) = o;
            }
        }
    }
}

// ---- kernel 2: fused 4-layer MLP per 64-pair tile --------------------------
__global__ __launch_bounds__(TPB, 2) void mlp_kernel(
    const float* __restrict__ positive, const float* __restrict__ negatives,
    const float* __restrict__ b2, const float* __restrict__ b3,
    const float* __restrict__ W4, const float* __restrict__ b4, int B) {
    extern __shared__ float smem[];
    float* buf = smem;              // [BM][PAD] activation buffer (reused)
    float* sW0 = smem + BM * PAD;   // ping-pong weight buffers [KT][256]
    float* sW1 = sW0 + KT * 256;
    const int tid = threadIdx.x;
    const int tx = tid & 15, ty = tid >> 4;
    const int P = B * CAND;
    const int p0 = blockIdx.x * BM;

    // Load Y tile (positive for c==0, negatives otherwise)
    for (int i = tid; i < BM * (D / 4); i += TPB) {
        int m = i >> 6, q = i & 63;
        int p = p0 + m; if (p >= P) p = P - 1;
        int r = p / CAND, c = p - r * CAND;
        const float* y = (c == 0) ? (positive + (size_t)r * D)
                                  : (negatives + ((size_t)r * NNEG + (c - 1)) * D);
        *reinterpret_cast<float4*>(&buf[m * PAD + q * 4]) =
            __ldg(reinterpret_cast<const float4*>(y) + q);
    }

    {   // layer 1: h1 = gelu(Y @ W1y^T + A[row])
        constexpr int NG = H1 / 64;
        constexpr int NF = 4 * NG;
        float acc[4 * NF];
        gemm_tile<H1, D>(buf, sW0, sW1, g_W1yT, acc);
#pragma unroll
        for (int mm = 0; mm < 4; ++mm) {
            int m = ty * 4 + mm;
            int p = p0 + m; if (p >= P) p = P - 1;
            int r = p / CAND;
#pragma unroll
            for (int v = 0; v < NG; ++v) {
                int j = v * 64 + 4 * tx;
                float4 av = __ldg(reinterpret_cast<const float4*>(&g_A[(size_t)r * H1 + j]));
                buf[m * PAD + j + 0] = gelu_exact(acc[mm * NF + 4 * v + 0] + av.x);
                buf[m * PAD + j + 1] = gelu_exact(acc[mm * NF + 4 * v + 1] + av.y);
                buf[m * PAD + j + 2] = gelu_exact(acc[mm * NF + 4 * v + 2] + av.z);
                buf[m * PAD + j + 3] = gelu_exact(acc[mm * NF + 4 * v + 3] + av.w);
            }
        }
    }
    {   // layer 2: h2 = gelu(h1 @ W2^T + b2)
        constexpr int NG = H2 / 64;
        constexpr int NF = 4 * NG;
        float acc[4 * NF];
        gemm_tile<H2, H1>(buf, sW0, sW1, g_W2T, acc);
#pragma unroll
        for (int v = 0; v < NG; ++v) {
            int j = v * 64 + 4 * tx;
            float4 bb = __ldg(reinterpret_cast<const float4*>(b2 + j));
#pragma unroll
            for (int mm = 0; mm < 4; ++mm) {
                int m = ty * 4 + mm;
                buf[m * PAD + j + 0] = gelu_exact(acc[mm * NF + 4 * v + 0] + bb.x);
                buf[m * PAD + j + 1] = gelu_exact(acc[mm * NF + 4 * v + 1] + bb.y);
                buf[m * PAD + j + 2] = gelu_exact(acc[mm * NF + 4 * v + 2] + bb.z);
                buf[m * PAD + j + 3] = gelu_exact(acc[mm * NF + 4 * v + 3] + bb.w);
            }
        }
    }
    {   // layer 3 + layer 4 fused: e = gelu(h2 @ W3^T + b3) . W4 + b4
        float acc[4 * 4];
        gemm_tile<H3, H2>(buf, sW0, sW1, g_W3T, acc);
        int j = 4 * tx;
        float4 bb = __ldg(reinterpret_cast<const float4*>(b3 + j));
        float4 w4 = __ldg(reinterpret_cast<const float4*>(W4 + j));
        float b4v = __ldg(b4);
#pragma unroll
        for (int mm = 0; mm < 4; ++mm) {
            float s;
            s  = gelu_exact(acc[mm * 4 + 0] + bb.x) * w4.x;
            s += gelu_exact(acc[mm * 4 + 1] + bb.y) * w4.y;
            s += gelu_exact(acc[mm * 4 + 2] + bb.z) * w4.z;
            s += gelu_exact(acc[mm * 4 + 3] + bb.w) * w4.w;
#pragma unroll
            for (int off = 8; off > 0; off >>= 1)
                s += __shfl_xor_sync(0xFFFFFFFFu, s, off);
            if (tx == 0) {
                int p = p0 + ty * 4 + mm;
                if (p < P) g_E[p] = s + b4v;
            }
        }
    }
}

// ---- kernel 3: per-row softmax/loss/argmin stats ---------------------------
__global__ void rowstats_kernel(int B) {
    int r = blockIdx.x * blockDim.x + threadIdx.x;
    if (r >= B) return;
    float e[CAND];
#pragma unroll
    for (int i = 0; i < CAND; ++i) e[i] = g_E[r * CAND + i];

    float l0 = -e[0] * TEMP_INV;
    float mx = l0;
#pragma unroll
    for (int i = 1; i < CAND; ++i) mx = fmaxf(mx, -e[i] * TEMP_INV);
    float s = 0.0f;
#pragma unroll
    for (int i = 0; i < CAND; ++i) s += expf(-e[i] * TEMP_INV - mx);
    float lse = mx + logf(s);

    float negs = 0.0f;
#pragma unroll
    for (int i = 1; i < CAND; ++i) negs += e[i];

    int am = 0; float best = e[0];
#pragma unroll
    for (int i = 1; i < CAND; ++i)
        if (e[i] < best) { best = e[i]; am = i; }

    g_row[0 * BMAX + r] = lse - l0;
    g_row[1 * BMAX + r] = e[0];
    g_row[2 * BMAX + r] = negs;
    g_row[3 * BMAX + r] = (am == 0) ? 1.0f : 0.0f;
}

// ---- kernel 4: deterministic single-block reduction ------------------------
__global__ void reduce_kernel(float* __restrict__ out, int B) {
    __shared__ float sred[1024];
    const int tid = threadIdx.x;
    float totals[4];
    for (int v = 0; v < 4; ++v) {
        float s = 0.0f;
        for (int i = tid; i < B; i += 1024) s += g_row[v * BMAX + i];
        sred[tid] = s;
        __syncthreads();
        for (int off = 512; off > 0; off >>= 1) {
            if (tid < off) sred[tid] += sred[tid + off];
            __syncthreads();
        }
        totals[v] = sred[0];
        __syncthreads();
    }
    if (tid == 0) {
        const float fB = (float)B;
        out[0] = totals[0] / fB;             // loss
        out[1] = totals[1] / fB;             // pos_energy
        out[2] = totals[2] / (fB * NNEG);    // neg_energy
        out[3] = totals[3] / fB;             // accuracy
    }
}

// ---------------------------------------------------------------------------
extern "C" void kernel_launch(void* const* d_in, const int* in_sizes, int n_in,
                              void* d_out, int out_size) {
    const float* anchor    = (const float*)d_in[0];
    const float* positive  = (const float*)d_in[1];
    const float* negatives = (const float*)d_in[2];
    const float* W1        = (const float*)d_in[3];
    const float* b1        = (const float*)d_in[4];
    const float* W2        = (const float*)d_in[5];
    const float* b2        = (const float*)d_in[6];
    const float* W3        = (const float*)d_in[7];
    const float* b3        = (const float*)d_in[8];
    const float* W4        = (const float*)d_in[9];
    const float* b4        = (const float*)d_in[10];
    float* out = (float*)d_out;

    int B = in_sizes[0] / D;
    if (B > BMAX) B = BMAX;
    const int P = B * CAND;

    const int smem = (BM * PAD + 2 * KT * 256) * (int)sizeof(float);  // 99328 B
    cudaFuncSetAttribute(anchor_kernel, cudaFuncAttributeMaxDynamicSharedMemorySize, smem);
    cudaFuncSetAttribute(mlp_kernel,    cudaFuncAttributeMaxDynamicSharedMemorySize, smem);

    prep_weights<<<(D * H1 + 255) / 256, 256>>>(W1, W2, W3);
    anchor_kernel<<<(B + BM - 1) / BM, TPB, smem>>>(anchor, b1, B);
    mlp_kernel<<<(P + BM - 1) / BM, TPB, smem>>>(positive, negatives, b2, b3, W4, b4, B);
    rowstats_kernel<<<(B + 255) / 256, 256>>>(B);
    reduce_kernel<<<1, 1024>>>(out, B);
}